// round 13
// baseline (speedup 1.0000x reference)
#include <cuda_runtime.h>
#include <cuda_fp16.h>

// ---------------- problem constants ----------------
#define NMAX 100000
#define EMAX 3200000
#define F 64

// ---------------- device scratch (no allocs allowed) ----------------
__device__ __align__(16)  int   g_deg[NMAX];       // zeroed at tail of k_final (and at module load)
__device__ __align__(16)  int   g_rowptr[NMAX + 1];
__device__ __align__(16)  int   g_cursor[NMAX];
__device__ __align__(16)  int   g_col[EMAX];
__device__ __align__(16)  float g_h  [NMAX * F];   // h (fp32, unscaled)
__device__ __align__(128) unsigned g_g0h[NMAX * 32]; // g0 = h*dinv, half2 rows (128B/row)
__device__ __align__(128) unsigned g_g1h[NMAX * 32]; // g1 half2 rows (gather operand pass 1)
__device__ __align__(16)  float g_g1f[NMAX * F];   // g1 fp32 (self term pass1 + final)
__device__ __align__(16)  float g_g2f[NMAX * F];   // g2 fp32 (final)

// ---------------- kernels ----------------

// no-op: shifts k_fillmlp to per-call launch index 3 (the ncu capture slot)
__global__ void k_nop(int dummy) { (void)dummy; }

__global__ void k_hist(const int* __restrict__ dst, int e) {
    for (int i = blockIdx.x * blockDim.x + threadIdx.x; i < e;
         i += gridDim.x * blockDim.x) {
        int d = dst[i];
        if (d >= 0 && d < NMAX) atomicAdd(&g_deg[d], 1);
    }
}

// single-block INTEGER-ONLY scan: rowptr (exclusive) + cursor copy.
__global__ void k_scan(int n) {
    __shared__ int ssum[1024];
    int t = threadIdx.x;
    int chunk = (n + 1023) >> 10;
    int beg = t * chunk;
    int end = min(n, beg + chunk);
    int s = 0;
    for (int i = beg; i < end; i++) s += g_deg[i];
    ssum[t] = s;
    __syncthreads();
    for (int off = 1; off < 1024; off <<= 1) {
        int v = (t >= off) ? ssum[t - off] : 0;
        __syncthreads();
        ssum[t] += v;
        __syncthreads();
    }
    int running = ssum[t] - s;  // exclusive prefix
    for (int i = beg; i < end; i++) {
        g_rowptr[i] = running;
        g_cursor[i] = running;
        running += g_deg[i];
    }
    if (t == 1023) g_rowptr[n] = ssum[1023];
}

// Fused fill + MLP, 2 nodes per thread in the MLP body (halves LDS.128 per FMA).
// Blocks [0, mlpB): MLP (256 threads x 2 nodes = 512 nodes/block).
// Blocks [mlpB, mlpB+fillB): CSR fill (256 edges/block).
__global__ void __launch_bounds__(256)
k_fillmlp(const int* __restrict__ src, const int* __restrict__ dst, int e,
          const float* __restrict__ X,
          const float* __restrict__ W1, const float* __restrict__ b1,
          const float* __restrict__ W2, const float* __restrict__ b2,
          int n, int mlpB) {
    int tid = threadIdx.x;
    int fb = (int)blockIdx.x - mlpB;

    if (fb >= 0) {
        // ---- fill body ----
        int i = fb * 256 + tid;
        if (i < e) {
            int d = dst[i];
            if (d >= 0 && d < NMAX) {
                int pos = atomicAdd(&g_cursor[d], 1);
                if (pos >= 0 && pos < EMAX) g_col[pos] = src[i];
            }
        }
        return;
    }

    // ---- MLP body: h = relu(relu(X@W1+b1)@W2+b2); g0h = half2(h*dinv) ----
    __shared__ float4 w1s[F * 16];
    __shared__ float4 w2s[F * 16];
    __shared__ float  b1s[F], b2s[F];
    for (int i = tid; i < F * 16; i += 256) {
        w1s[i] = ((const float4*)W1)[i];
        w2s[i] = ((const float4*)W2)[i];
    }
    if (tid < F) { b1s[tid] = b1[tid]; b2s[tid] = b2[tid]; }
    __syncthreads();

    int nodeA = blockIdx.x * 512 + tid;
    int nodeB = nodeA + 256;
    if (nodeA >= n) return;
    bool vB = (nodeB < n);
    size_t nB = vB ? (size_t)nodeB : (size_t)nodeA;  // safe dummy

    const float4* xpA = (const float4*)(X + (size_t)nodeA * F);
    const float4* xpB = (const float4*)(X + nB * F);

    float hA[F], hB[F];
#pragma unroll
    for (int j = 0; j < F; j++) { float bj = b1s[j]; hA[j] = bj; hB[j] = bj; }

    for (int k4 = 0; k4 < 16; k4++) {
        float4 xvA = __ldg(xpA + k4);
        float4 xvB = __ldg(xpB + k4);
#pragma unroll
        for (int c = 0; c < 4; c++) {
            float xkA = (c == 0) ? xvA.x : (c == 1) ? xvA.y : (c == 2) ? xvA.z : xvA.w;
            float xkB = (c == 0) ? xvB.x : (c == 1) ? xvB.y : (c == 2) ? xvB.z : xvB.w;
            int k = k4 * 4 + c;
#pragma unroll
            for (int j4 = 0; j4 < 16; j4++) {
                float4 w = w1s[k * 16 + j4];
                hA[4 * j4 + 0] = fmaf(xkA, w.x, hA[4 * j4 + 0]);
                hA[4 * j4 + 1] = fmaf(xkA, w.y, hA[4 * j4 + 1]);
                hA[4 * j4 + 2] = fmaf(xkA, w.z, hA[4 * j4 + 2]);
                hA[4 * j4 + 3] = fmaf(xkA, w.w, hA[4 * j4 + 3]);
                hB[4 * j4 + 0] = fmaf(xkB, w.x, hB[4 * j4 + 0]);
                hB[4 * j4 + 1] = fmaf(xkB, w.y, hB[4 * j4 + 1]);
                hB[4 * j4 + 2] = fmaf(xkB, w.z, hB[4 * j4 + 2]);
                hB[4 * j4 + 3] = fmaf(xkB, w.w, hB[4 * j4 + 3]);
            }
        }
    }
#pragma unroll
    for (int j = 0; j < F; j++) { hA[j] = fmaxf(hA[j], 0.0f); hB[j] = fmaxf(hB[j], 0.0f); }

    // degree-derived scalars (distributed MUFUs)
    int dgA = __ldg(&g_deg[nodeA]);
    int dgB = __ldg(&g_deg[(int)nB]);
    float dvA = rsqrtf((float)(dgA < 1 ? 1 : dgA));
    float dvB = rsqrtf((float)(dgB < 1 ? 1 : dgB));

    float4* hpA = (float4*)(g_h + (size_t)nodeA * F);
    float4* hpB = (float4*)(g_h + nB * F);
    uint2*  gpA = (uint2*)(g_g0h + (size_t)nodeA * 32);
    uint2*  gpB = (uint2*)(g_g0h + nB * 32);
    for (int j4 = 0; j4 < 16; j4++) {
        float4 aA = make_float4(b2s[4 * j4], b2s[4 * j4 + 1], b2s[4 * j4 + 2], b2s[4 * j4 + 3]);
        float4 aB = aA;
#pragma unroll
        for (int k = 0; k < F; k++) {
            float4 w = w2s[k * 16 + j4];
            float hkA = hA[k];
            float hkB = hB[k];
            aA.x = fmaf(hkA, w.x, aA.x);
            aA.y = fmaf(hkA, w.y, aA.y);
            aA.z = fmaf(hkA, w.z, aA.z);
            aA.w = fmaf(hkA, w.w, aA.w);
            aB.x = fmaf(hkB, w.x, aB.x);
            aB.y = fmaf(hkB, w.y, aB.y);
            aB.z = fmaf(hkB, w.z, aB.z);
            aB.w = fmaf(hkB, w.w, aB.w);
        }
        aA.x = fmaxf(aA.x, 0.0f); aA.y = fmaxf(aA.y, 0.0f);
        aA.z = fmaxf(aA.z, 0.0f); aA.w = fmaxf(aA.w, 0.0f);
        aB.x = fmaxf(aB.x, 0.0f); aB.y = fmaxf(aB.y, 0.0f);
        aB.z = fmaxf(aB.z, 0.0f); aB.w = fmaxf(aB.w, 0.0f);
        hpA[j4] = aA;
        __half2 pA0 = __floats2half2_rn(aA.x * dvA, aA.y * dvA);
        __half2 pA1 = __floats2half2_rn(aA.z * dvA, aA.w * dvA);
        uint2 uA;
        uA.x = *reinterpret_cast<unsigned*>(&pA0);
        uA.y = *reinterpret_cast<unsigned*>(&pA1);
        gpA[j4] = uA;
        if (vB) {
            hpB[j4] = aB;
            __half2 pB0 = __floats2half2_rn(aB.x * dvB, aB.y * dvB);
            __half2 pB1 = __floats2half2_rn(aB.z * dvB, aB.w * dvB);
            uint2 uB;
            uB.x = *reinterpret_cast<unsigned*>(&pB0);
            uB.y = *reinterpret_cast<unsigned*>(&pB1);
            gpB[j4] = uB;
        }
    }
}

// Scaled-space Laplacian, fp16 gather rows (one 128B line per neighbor row):
//   out[d] = self[d]*selfScale - invdeg[d] * sum_{s in N_in(d)} gh[s]
// one warp per node, 32 lanes x half2 (64 feats/row). Col tile prefetched.
// pass 0: gather g_g0h, self = g_h*dinv  -> g_g1f + g_g1h
// pass 1: gather g_g1h, self = g_g1f     -> g_g2f
__global__ void __launch_bounds__(256)
k_lap(int pass, int n) {
    const unsigned* inH;
    const float*    selfF;
    float*          outF;
    unsigned*       outH;
    if (pass == 0) { inH = g_g0h; selfF = g_h;   outF = g_g1f; outH = g_g1h; }
    else           { inH = g_g1h; selfF = g_g1f; outF = g_g2f; outH = 0;     }

    int warp = threadIdx.x >> 5;
    int lane = threadIdx.x & 31;
    int node = blockIdx.x * 8 + warp;
    if (node >= n) return;  // warp-uniform exit

    int beg = __ldg(&g_rowptr[node]);
    int end = __ldg(&g_rowptr[node + 1]);

    int dg = __ldg(&g_deg[node]);
    float fd = (float)(dg < 1 ? 1 : dg);
    float idg = 1.0f / fd;
    float selfScale = (pass == 0) ? rsqrtf(fd) : 1.0f;

    float2 sf = __ldg(&((const float2*)selfF)[(size_t)node * 32 + lane]);

    float ax = 0.0f, ay = 0.0f;

    int c_cur = 0;
    {
        int idx = beg + lane;
        if (idx < end) c_cur = __ldg(&g_col[idx]);
    }

    for (int base = beg; base < end; base += 32) {
        int c_next = 0;
        int nbase = base + 32;
        if (nbase < end) {
            int idx = nbase + lane;
            if (idx < end) c_next = __ldg(&g_col[idx]);
        }
        int cnt = min(32, end - base);
#pragma unroll 8
        for (int i = 0; i < cnt; i++) {
            int s = __shfl_sync(0xffffffffu, c_cur, i);
            unsigned vbits = __ldg(&inH[(size_t)s * 32 + lane]);
            __half2 vh = *reinterpret_cast<__half2*>(&vbits);
            float2 vf = __half22float2(vh);
            ax += vf.x;
            ay += vf.y;
        }
        c_cur = c_next;
    }

    float2 o;
    o.x = sf.x * selfScale - idg * ax;
    o.y = sf.y * selfScale - idg * ay;
    ((float2*)outF)[(size_t)node * 32 + lane] = o;
    if (outH) {
        __half2 p = __floats2half2_rn(o.x, o.y);
        outH[(size_t)node * 32 + lane] = *reinterpret_cast<unsigned*>(&p);
    }
}

// Fused tail, 2 nodes per thread (halves LDS.128 per FMA):
// Wa=3A, Wb=-3A+3B, Wc=.75A-1.5B+.75C from W3;
// f1 = g1*dsqrt, f2 = g2*dsqrt; y = relu(h@Wa + f1@Wb + f2@Wc + b3); out = y@W4 + b4.
// Reads deg -> dsqrt, then re-zeros g_deg for next call (replay invariant).
__global__ void __launch_bounds__(128)
k_final(const float* __restrict__ W3, const float* __restrict__ b3,
        const float* __restrict__ W4, const float* __restrict__ b4,
        float* __restrict__ out, int n) {
    __shared__ float4 was[F * 16];
    __shared__ float4 wbs[F * 16];
    __shared__ float4 wcs[F * 16];  // 48KB static
    int tid = threadIdx.x;
    {
        float* wa = (float*)was;
        float* wb = (float*)wbs;
        float* wc = (float*)wcs;
        for (int i = tid; i < F * F; i += 128) {
            float a = W3[i];
            float b = W3[F * F + i];
            float c = W3[2 * F * F + i];
            wa[i] = 3.0f * a;
            wb[i] = -3.0f * a + 3.0f * b;
            wc[i] = 0.75f * a - 1.5f * b + 0.75f * c;
        }
    }
    __syncthreads();

    int node0 = blockIdx.x * 256 + tid;
    int node1 = node0 + 128;
    if (node0 >= n) return;
    bool v1 = (node1 < n);
    size_t n1 = v1 ? (size_t)node1 : (size_t)node0;  // safe dummy

    int dg0 = g_deg[node0];
    g_deg[node0] = 0;
    float ds0 = sqrtf((float)(dg0 < 1 ? 1 : dg0));
    float ds1 = 0.0f;
    if (v1) {
        int dg1 = g_deg[node1];
        g_deg[node1] = 0;
        ds1 = sqrtf((float)(dg1 < 1 ? 1 : dg1));
    }

    float y0[F], y1[F];
#pragma unroll
    for (int j = 0; j < F; j++) { float bj = b3[j]; y0[j] = bj; y1[j] = bj; }

    const float4* hp0  = (const float4*)(g_h   + (size_t)node0 * F);
    const float4* g1p0 = (const float4*)(g_g1f + (size_t)node0 * F);
    const float4* g2p0 = (const float4*)(g_g2f + (size_t)node0 * F);
    const float4* hp1  = (const float4*)(g_h   + n1 * F);
    const float4* g1p1 = (const float4*)(g_g1f + n1 * F);
    const float4* g2p1 = (const float4*)(g_g2f + n1 * F);

    for (int k4 = 0; k4 < 16; k4++) {
        float4 hv0  = __ldg(hp0  + k4);
        float4 f1v0 = __ldg(g1p0 + k4);
        float4 f2v0 = __ldg(g2p0 + k4);
        float4 hv1  = __ldg(hp1  + k4);
        float4 f1v1 = __ldg(g1p1 + k4);
        float4 f2v1 = __ldg(g2p1 + k4);
        f1v0.x *= ds0; f1v0.y *= ds0; f1v0.z *= ds0; f1v0.w *= ds0;
        f2v0.x *= ds0; f2v0.y *= ds0; f2v0.z *= ds0; f2v0.w *= ds0;
        f1v1.x *= ds1; f1v1.y *= ds1; f1v1.z *= ds1; f1v1.w *= ds1;
        f2v1.x *= ds1; f2v1.y *= ds1; f2v1.z *= ds1; f2v1.w *= ds1;
#pragma unroll
        for (int c = 0; c < 4; c++) {
            float hk0  = (c == 0) ? hv0.x  : (c == 1) ? hv0.y  : (c == 2) ? hv0.z  : hv0.w;
            float f1k0 = (c == 0) ? f1v0.x : (c == 1) ? f1v0.y : (c == 2) ? f1v0.z : f1v0.w;
            float f2k0 = (c == 0) ? f2v0.x : (c == 1) ? f2v0.y : (c == 2) ? f2v0.z : f2v0.w;
            float hk1  = (c == 0) ? hv1.x  : (c == 1) ? hv1.y  : (c == 2) ? hv1.z  : hv1.w;
            float f1k1 = (c == 0) ? f1v1.x : (c == 1) ? f1v1.y : (c == 2) ? f1v1.z : f1v1.w;
            float f2k1 = (c == 0) ? f2v1.x : (c == 1) ? f2v1.y : (c == 2) ? f2v1.z : f2v1.w;
            int k = k4 * 4 + c;
#pragma unroll
            for (int j4 = 0; j4 < 16; j4++) {
                float4 wa = was[k * 16 + j4];
                float4 wb = wbs[k * 16 + j4];
                float4 wc = wcs[k * 16 + j4];
                y0[4 * j4 + 0] = fmaf(hk0, wa.x, fmaf(f1k0, wb.x, fmaf(f2k0, wc.x, y0[4 * j4 + 0])));
                y0[4 * j4 + 1] = fmaf(hk0, wa.y, fmaf(f1k0, wb.y, fmaf(f2k0, wc.y, y0[4 * j4 + 1])));
                y0[4 * j4 + 2] = fmaf(hk0, wa.z, fmaf(f1k0, wb.z, fmaf(f2k0, wc.z, y0[4 * j4 + 2])));
                y0[4 * j4 + 3] = fmaf(hk0, wa.w, fmaf(f1k0, wb.w, fmaf(f2k0, wc.w, y0[4 * j4 + 3])));
                y1[4 * j4 + 0] = fmaf(hk1, wa.x, fmaf(f1k1, wb.x, fmaf(f2k1, wc.x, y1[4 * j4 + 0])));
                y1[4 * j4 + 1] = fmaf(hk1, wa.y, fmaf(f1k1, wb.y, fmaf(f2k1, wc.y, y1[4 * j4 + 1])));
                y1[4 * j4 + 2] = fmaf(hk1, wa.z, fmaf(f1k1, wb.z, fmaf(f2k1, wc.z, y1[4 * j4 + 2])));
                y1[4 * j4 + 3] = fmaf(hk1, wa.w, fmaf(f1k1, wb.w, fmaf(f2k1, wc.w, y1[4 * j4 + 3])));
            }
        }
    }

    float b40 = b4[0];
    float b41 = b4[1];
    float o00 = b40, o01 = b41, o10 = b40, o11 = b41;
#pragma unroll
    for (int j = 0; j < F; j++) {
        float w0 = W4[j * 2 + 0];
        float w1 = W4[j * 2 + 1];
        float yj0 = fmaxf(y0[j], 0.0f);
        float yj1 = fmaxf(y1[j], 0.0f);
        o00 = fmaf(yj0, w0, o00);
        o01 = fmaf(yj0, w1, o01);
        o10 = fmaf(yj1, w0, o10);
        o11 = fmaf(yj1, w1, o11);
    }
    ((float2*)out)[node0] = make_float2(o00, o01);
    if (v1) ((float2*)out)[node1] = make_float2(o10, o11);
}

// ---------------- launcher ----------------
extern "C" void kernel_launch(void* const* d_in, const int* in_sizes, int n_in,
                              void* d_out, int out_size) {
    const float* in_feat = (const float*)d_in[0];
    const int*   src     = (const int*)d_in[1];
    const int*   dst     = (const int*)d_in[2];
    const float* W1 = (const float*)d_in[3];
    const float* b1 = (const float*)d_in[4];
    const float* W2 = (const float*)d_in[5];
    const float* b2 = (const float*)d_in[6];
    const float* W3 = (const float*)d_in[7];
    const float* b3 = (const float*)d_in[8];
    const float* W4 = (const float*)d_in[9];
    const float* b4 = (const float*)d_in[10];

    int n = in_sizes[0] / F;
    if (n > NMAX) n = NMAX;
    int e = in_sizes[1];
    if (e > EMAX) e = EMAX;

    int mlpB  = (n + 511) / 512;
    int fillB = (e + 255) / 256;

    // g_deg is zero at first call (module load) and re-zeroed by k_final each call.
    k_nop<<<1, 32>>>(0);                                                    // launch 0 (slot shim)
    k_hist<<<(e + 255) / 256, 256>>>(dst, e);                               // launch 1
    k_scan<<<1, 1024>>>(n);                                                 // launch 2
    k_fillmlp<<<mlpB + fillB, 256>>>(src, dst, e, in_feat,
                                     W1, b1, W2, b2, n, mlpB);              // launch 3 (ncu slot)
    k_lap<<<(n + 7) / 8, 256>>>(0, n);                                      // launch 4
    k_lap<<<(n + 7) / 8, 256>>>(1, n);                                      // launch 5
    k_final<<<(n + 255) / 256, 128>>>(W3, b3, W4, b4, (float*)d_out, n);    // launch 6
}

// round 14
// speedup vs baseline: 1.1773x; 1.1773x over previous
#include <cuda_runtime.h>
#include <cuda_fp16.h>

// ---------------- problem constants ----------------
#define NMAX 100000
#define EMAX 3200000
#define F 64

// ---------------- device scratch (no allocs allowed) ----------------
__device__ __align__(16)  int   g_deg[NMAX];       // zeroed at tail of k_final (and at module load)
__device__ __align__(16)  int   g_rowptr[NMAX + 1];
__device__ __align__(16)  int   g_cursor[NMAX];
__device__ __align__(16)  int   g_col[EMAX];
__device__ __align__(16)  float g_h  [NMAX * F];   // h (fp32, unscaled)
__device__ __align__(128) unsigned g_g0h[NMAX * 32]; // g0 = h*dinv, half2 rows (128B/row)
__device__ __align__(128) unsigned g_g1h[NMAX * 32]; // g1 half2 rows (gather operand pass 1)
__device__ __align__(16)  float g_g1f[NMAX * F];   // g1 fp32 (self term pass1 + final)
__device__ __align__(16)  float g_g2f[NMAX * F];   // g2 fp32 (final)

// ---------------- kernels ----------------

// no-op: shifts k_fillmlp to per-call launch index 3 (the ncu capture slot)
__global__ void k_nop(int dummy) { (void)dummy; }

// int4-vectorized histogram: 4 edges per thread
__global__ void k_hist(const int* __restrict__ dst, int e) {
    int t = blockIdx.x * blockDim.x + threadIdx.x;
    int i = t * 4;
    if (i + 3 < e) {
        int4 d4 = __ldg((const int4*)(dst + i));
        if (d4.x >= 0 && d4.x < NMAX) atomicAdd(&g_deg[d4.x], 1);
        if (d4.y >= 0 && d4.y < NMAX) atomicAdd(&g_deg[d4.y], 1);
        if (d4.z >= 0 && d4.z < NMAX) atomicAdd(&g_deg[d4.z], 1);
        if (d4.w >= 0 && d4.w < NMAX) atomicAdd(&g_deg[d4.w], 1);
    } else {
        for (int k = i; k < e; k++) {
            int d = __ldg(dst + k);
            if (d >= 0 && d < NMAX) atomicAdd(&g_deg[d], 1);
        }
    }
}

// single-block INTEGER-ONLY scan: rowptr (exclusive) + cursor copy.
__global__ void k_scan(int n) {
    __shared__ int ssum[1024];
    int t = threadIdx.x;
    int chunk = (n + 1023) >> 10;
    int beg = t * chunk;
    int end = min(n, beg + chunk);
    int s = 0;
    for (int i = beg; i < end; i++) s += g_deg[i];
    ssum[t] = s;
    __syncthreads();
    for (int off = 1; off < 1024; off <<= 1) {
        int v = (t >= off) ? ssum[t - off] : 0;
        __syncthreads();
        ssum[t] += v;
        __syncthreads();
    }
    int running = ssum[t] - s;  // exclusive prefix
    for (int i = beg; i < end; i++) {
        g_rowptr[i] = running;
        g_cursor[i] = running;
        running += g_deg[i];
    }
    if (t == 1023) g_rowptr[n] = ssum[1023];
}

// Fused fill + MLP. Blocks [0, mlpB): MLP (256 threads = 256 nodes/block).
// Blocks [mlpB, mlpB+fillB): CSR fill, int4-vectorized (4 edges/thread,
// 1024 edges/block). Both depend only on k_scan outputs; mutually independent.
__global__ void __launch_bounds__(256)
k_fillmlp(const int* __restrict__ src, const int* __restrict__ dst, int e,
          const float* __restrict__ X,
          const float* __restrict__ W1, const float* __restrict__ b1,
          const float* __restrict__ W2, const float* __restrict__ b2,
          int n, int mlpB) {
    int tid = threadIdx.x;
    int fb = (int)blockIdx.x - mlpB;

    if (fb >= 0) {
        // ---- fill body (int4) ----
        int i = fb * 1024 + tid * 4;
        if (i + 3 < e) {
            int4 d4 = __ldg((const int4*)(dst + i));
            int4 s4 = __ldg((const int4*)(src + i));
            if (d4.x >= 0 && d4.x < NMAX) {
                int p = atomicAdd(&g_cursor[d4.x], 1);
                if (p >= 0 && p < EMAX) g_col[p] = s4.x;
            }
            if (d4.y >= 0 && d4.y < NMAX) {
                int p = atomicAdd(&g_cursor[d4.y], 1);
                if (p >= 0 && p < EMAX) g_col[p] = s4.y;
            }
            if (d4.z >= 0 && d4.z < NMAX) {
                int p = atomicAdd(&g_cursor[d4.z], 1);
                if (p >= 0 && p < EMAX) g_col[p] = s4.z;
            }
            if (d4.w >= 0 && d4.w < NMAX) {
                int p = atomicAdd(&g_cursor[d4.w], 1);
                if (p >= 0 && p < EMAX) g_col[p] = s4.w;
            }
        } else {
            for (int k = i; k < e; k++) {
                int d = __ldg(dst + k);
                if (d >= 0 && d < NMAX) {
                    int p = atomicAdd(&g_cursor[d], 1);
                    if (p >= 0 && p < EMAX) g_col[p] = __ldg(src + k);
                }
            }
        }
        return;
    }

    // ---- MLP body: h = relu(relu(X@W1+b1)@W2+b2); g0h = half2(h*dinv) ----
    __shared__ float4 w1s[F * 16];
    __shared__ float4 w2s[F * 16];
    __shared__ float  b1s[F], b2s[F];
    for (int i = tid; i < F * 16; i += 256) {
        w1s[i] = ((const float4*)W1)[i];
        w2s[i] = ((const float4*)W2)[i];
    }
    if (tid < F) { b1s[tid] = b1[tid]; b2s[tid] = b2[tid]; }
    __syncthreads();

    int node = blockIdx.x * 256 + tid;
    if (node >= n) return;

    const float4* xp = (const float4*)(X + (size_t)node * F);

    float h1[F];
#pragma unroll
    for (int j = 0; j < F; j++) h1[j] = b1s[j];

    for (int k4 = 0; k4 < 16; k4++) {
        float4 xv = __ldg(xp + k4);
#pragma unroll
        for (int c = 0; c < 4; c++) {
            float xk = (c == 0) ? xv.x : (c == 1) ? xv.y : (c == 2) ? xv.z : xv.w;
            int k = k4 * 4 + c;
#pragma unroll
            for (int j4 = 0; j4 < 16; j4++) {
                float4 w = w1s[k * 16 + j4];
                h1[4 * j4 + 0] = fmaf(xk, w.x, h1[4 * j4 + 0]);
                h1[4 * j4 + 1] = fmaf(xk, w.y, h1[4 * j4 + 1]);
                h1[4 * j4 + 2] = fmaf(xk, w.z, h1[4 * j4 + 2]);
                h1[4 * j4 + 3] = fmaf(xk, w.w, h1[4 * j4 + 3]);
            }
        }
    }
#pragma unroll
    for (int j = 0; j < F; j++) h1[j] = fmaxf(h1[j], 0.0f);

    // degree-derived scalar computed here (distributed, 1 MUFU per node)
    int dg = __ldg(&g_deg[node]);
    float fd = (float)(dg < 1 ? 1 : dg);
    float dv = rsqrtf(fd);

    float4* hp = (float4*)(g_h + (size_t)node * F);
    uint2*  gp = (uint2*)(g_g0h + (size_t)node * 32);
    for (int j4 = 0; j4 < 16; j4++) {
        float4 acc = make_float4(b2s[4 * j4], b2s[4 * j4 + 1], b2s[4 * j4 + 2], b2s[4 * j4 + 3]);
#pragma unroll
        for (int k = 0; k < F; k++) {
            float4 w = w2s[k * 16 + j4];
            float hk = h1[k];
            acc.x = fmaf(hk, w.x, acc.x);
            acc.y = fmaf(hk, w.y, acc.y);
            acc.z = fmaf(hk, w.z, acc.z);
            acc.w = fmaf(hk, w.w, acc.w);
        }
        acc.x = fmaxf(acc.x, 0.0f);
        acc.y = fmaxf(acc.y, 0.0f);
        acc.z = fmaxf(acc.z, 0.0f);
        acc.w = fmaxf(acc.w, 0.0f);
        hp[j4] = acc;
        __half2 p0 = __floats2half2_rn(acc.x * dv, acc.y * dv);
        __half2 p1 = __floats2half2_rn(acc.z * dv, acc.w * dv);
        uint2 u;
        u.x = *reinterpret_cast<unsigned*>(&p0);
        u.y = *reinterpret_cast<unsigned*>(&p1);
        gp[j4] = u;
    }
}

// Scaled-space Laplacian, fp16 gather rows (one 128B line per neighbor row):
//   out[d] = self[d]*selfScale - invdeg[d] * sum_{s in N_in(d)} gh[s]
// one warp per node, 32 lanes x half2 (64 feats/row). Col tile prefetched.
// pass 0: gather g_g0h, self = g_h*dinv  -> g_g1f + g_g1h
// pass 1: gather g_g1h, self = g_g1f     -> g_g2f
__global__ void __launch_bounds__(256)
k_lap(int pass, int n) {
    const unsigned* inH;
    const float*    selfF;
    float*          outF;
    unsigned*       outH;
    if (pass == 0) { inH = g_g0h; selfF = g_h;   outF = g_g1f; outH = g_g1h; }
    else           { inH = g_g1h; selfF = g_g1f; outF = g_g2f; outH = 0;     }

    int warp = threadIdx.x >> 5;
    int lane = threadIdx.x & 31;
    int node = blockIdx.x * 8 + warp;
    if (node >= n) return;  // warp-uniform exit

    int beg = __ldg(&g_rowptr[node]);
    int end = __ldg(&g_rowptr[node + 1]);

    int dg = __ldg(&g_deg[node]);
    float fd = (float)(dg < 1 ? 1 : dg);
    float idg = 1.0f / fd;
    float selfScale = (pass == 0) ? rsqrtf(fd) : 1.0f;

    float2 sf = __ldg(&((const float2*)selfF)[(size_t)node * 32 + lane]);

    float ax = 0.0f, ay = 0.0f;

    int c_cur = 0;
    {
        int idx = beg + lane;
        if (idx < end) c_cur = __ldg(&g_col[idx]);
    }

    for (int base = beg; base < end; base += 32) {
        int c_next = 0;
        int nbase = base + 32;
        if (nbase < end) {
            int idx = nbase + lane;
            if (idx < end) c_next = __ldg(&g_col[idx]);
        }
        int cnt = min(32, end - base);
#pragma unroll 8
        for (int i = 0; i < cnt; i++) {
            int s = __shfl_sync(0xffffffffu, c_cur, i);
            unsigned vbits = __ldg(&inH[(size_t)s * 32 + lane]);
            __half2 vh = *reinterpret_cast<__half2*>(&vbits);
            float2 vf = __half22float2(vh);
            ax += vf.x;
            ay += vf.y;
        }
        c_cur = c_next;
    }

    float2 o;
    o.x = sf.x * selfScale - idg * ax;
    o.y = sf.y * selfScale - idg * ay;
    ((float2*)outF)[(size_t)node * 32 + lane] = o;
    if (outH) {
        __half2 p = __floats2half2_rn(o.x, o.y);
        outH[(size_t)node * 32 + lane] = *reinterpret_cast<unsigned*>(&p);
    }
}

// Fused tail (wcomb folded in), 1 node per thread (measured-good config):
// Wa=3A, Wb=-3A+3B, Wc=.75A-1.5B+.75C from W3;
// f1 = g1*dsqrt, f2 = g2*dsqrt; y = relu(h@Wa + f1@Wb + f2@Wc + b3); out = y@W4 + b4.
// Reads deg -> dsqrt, then re-zeros g_deg for the next call (replay invariant).
__global__ void __launch_bounds__(128)
k_final(const float* __restrict__ W3, const float* __restrict__ b3,
        const float* __restrict__ W4, const float* __restrict__ b4,
        float* __restrict__ out, int n) {
    __shared__ float4 was[F * 16];
    __shared__ float4 wbs[F * 16];
    __shared__ float4 wcs[F * 16];  // 48KB static
    int tid = threadIdx.x;
    {
        float* wa = (float*)was;
        float* wb = (float*)wbs;
        float* wc = (float*)wcs;
        for (int i = tid; i < F * F; i += 128) {
            float a = W3[i];
            float b = W3[F * F + i];
            float c = W3[2 * F * F + i];
            wa[i] = 3.0f * a;
            wb[i] = -3.0f * a + 3.0f * b;
            wc[i] = 0.75f * a - 1.5f * b + 0.75f * c;
        }
    }
    __syncthreads();

    int node = blockIdx.x * 128 + tid;
    if (node >= n) return;

    int dg = g_deg[node];
    g_deg[node] = 0;  // reset for next kernel_launch call (read-then-zero)
    float fd = (float)(dg < 1 ? 1 : dg);
    float ds = sqrtf(fd);

    float y[F];
#pragma unroll
    for (int j = 0; j < F; j++) y[j] = b3[j];

    const float4* hp  = (const float4*)(g_h   + (size_t)node * F);
    const float4* g1p = (const float4*)(g_g1f + (size_t)node * F);
    const float4* g2p = (const float4*)(g_g2f + (size_t)node * F);

    for (int k4 = 0; k4 < 16; k4++) {
        float4 hv  = __ldg(hp  + k4);
        float4 f1v = __ldg(g1p + k4);
        float4 f2v = __ldg(g2p + k4);
        f1v.x *= ds; f1v.y *= ds; f1v.z *= ds; f1v.w *= ds;
        f2v.x *= ds; f2v.y *= ds; f2v.z *= ds; f2v.w *= ds;
#pragma unroll
        for (int c = 0; c < 4; c++) {
            float hk  = (c == 0) ? hv.x  : (c == 1) ? hv.y  : (c == 2) ? hv.z  : hv.w;
            float f1k = (c == 0) ? f1v.x : (c == 1) ? f1v.y : (c == 2) ? f1v.z : f1v.w;
            float f2k = (c == 0) ? f2v.x : (c == 1) ? f2v.y : (c == 2) ? f2v.z : f2v.w;
            int k = k4 * 4 + c;
#pragma unroll
            for (int j4 = 0; j4 < 16; j4++) {
                float4 wa = was[k * 16 + j4];
                float4 wb = wbs[k * 16 + j4];
                float4 wc = wcs[k * 16 + j4];
                y[4 * j4 + 0] = fmaf(hk, wa.x, fmaf(f1k, wb.x, fmaf(f2k, wc.x, y[4 * j4 + 0])));
                y[4 * j4 + 1] = fmaf(hk, wa.y, fmaf(f1k, wb.y, fmaf(f2k, wc.y, y[4 * j4 + 1])));
                y[4 * j4 + 2] = fmaf(hk, wa.z, fmaf(f1k, wb.z, fmaf(f2k, wc.z, y[4 * j4 + 2])));
                y[4 * j4 + 3] = fmaf(hk, wa.w, fmaf(f1k, wb.w, fmaf(f2k, wc.w, y[4 * j4 + 3])));
            }
        }
    }

    float o0 = b4[0];
    float o1 = b4[1];
#pragma unroll
    for (int j = 0; j < F; j++) {
        float yj = fmaxf(y[j], 0.0f);
        o0 = fmaf(yj, W4[j * 2 + 0], o0);
        o1 = fmaf(yj, W4[j * 2 + 1], o1);
    }
    ((float2*)out)[node] = make_float2(o0, o1);
}

// ---------------- launcher ----------------
extern "C" void kernel_launch(void* const* d_in, const int* in_sizes, int n_in,
                              void* d_out, int out_size) {
    const float* in_feat = (const float*)d_in[0];
    const int*   src     = (const int*)d_in[1];
    const int*   dst     = (const int*)d_in[2];
    const float* W1 = (const float*)d_in[3];
    const float* b1 = (const float*)d_in[4];
    const float* W2 = (const float*)d_in[5];
    const float* b2 = (const float*)d_in[6];
    const float* W3 = (const float*)d_in[7];
    const float* b3 = (const float*)d_in[8];
    const float* W4 = (const float*)d_in[9];
    const float* b4 = (const float*)d_in[10];

    int n = in_sizes[0] / F;
    if (n > NMAX) n = NMAX;
    int e = in_sizes[1];
    if (e > EMAX) e = EMAX;

    int mlpB  = (n + 255) / 256;
    int fillB = (e + 1023) / 1024;   // 4 edges per thread
    int histB = (e + 1023) / 1024;

    // g_deg is zero at first call (module load) and re-zeroed by k_final each call.
    k_nop<<<1, 32>>>(0);                                                    // launch 0 (slot shim)
    k_hist<<<histB, 256>>>(dst, e);                                         // launch 1
    k_scan<<<1, 1024>>>(n);                                                 // launch 2
    k_fillmlp<<<mlpB + fillB, 256>>>(src, dst, e, in_feat,
                                     W1, b1, W2, b2, n, mlpB);              // launch 3 (ncu slot)
    k_lap<<<(n + 7) / 8, 256>>>(0, n);                                      // launch 4
    k_lap<<<(n + 7) / 8, 256>>>(1, n);                                      // launch 5
    k_final<<<(n + 127) / 128, 128>>>(W3, b3, W4, b4, (float*)d_out, n);    // launch 6
}